// round 1
// baseline (speedup 1.0000x reference)
#include <cuda_runtime.h>

// SNNAutoencoder: B=65536, D=512, H=64, L=16, T=8
// Inputs (metadata order): x[65536,512], W1[64,512], b1[64], W2[16,64], b2[16],
//                          W3[64,16], b3[64], W4[512,64], b4[512]
// Output: float32 [65536, 512]

#define B_TOTAL 65536

// Scratch (static device arrays — no allocation in kernel_launch)
__device__ float              g_hin[(size_t)B_TOTAL * 64];      // 16 MB
__device__ unsigned long long g_masks[(size_t)B_TOTAL * 8];     //  4 MB: [row][t] packed s3

// ---------------------------------------------------------------------------
// helpers: packed f32x2 math
// ---------------------------------------------------------------------------
__device__ __forceinline__ unsigned long long fma2(unsigned long long a,
                                                   unsigned long long b,
                                                   unsigned long long c) {
    unsigned long long d;
    asm("fma.rn.f32x2 %0, %1, %2, %3;" : "=l"(d) : "l"(a), "l"(b), "l"(c));
    return d;
}
__device__ __forceinline__ unsigned long long pack2f(float a, float b) {
    unsigned long long r;
    asm("mov.b64 %0, {%1, %2};" : "=l"(r) : "f"(a), "f"(b));
    return r;
}
__device__ __forceinline__ unsigned long long pack2u(unsigned a, unsigned b) {
    unsigned long long r;
    asm("mov.b64 %0, {%1, %2};" : "=l"(r) : "r"(a), "r"(b));
    return r;
}
__device__ __forceinline__ void unpack2(unsigned long long v, float& a, float& b) {
    asm("mov.b64 {%0, %1}, %2;" : "=f"(a), "=f"(b) : "l"(v));
}
__device__ __forceinline__ float sigmoidf(float z) {
    return 1.0f / (1.0f + __expf(-z));
}

// ---------------------------------------------------------------------------
// Kernel 1: h_in[B,64] = x[B,512] @ W1^T + b1     (FP32 tiled GEMM)
// Block: 256 threads, tile 64 rows x 64 cols, K chunks of 64.
// ---------------------------------------------------------------------------
__global__ void __launch_bounds__(256) k1_hin(const float* __restrict__ x,
                                              const float* __restrict__ W1,
                                              const float* __restrict__ b1) {
    __shared__ float xs[64][68];
    __shared__ float ws[64][68];
    const int tid = threadIdx.x;
    const int tx = tid & 15;        // col group: cols 4*tx..4*tx+3
    const int ty = tid >> 4;        // row group: rows 4*ty..4*ty+3
    const int rowBase = blockIdx.x * 64;

    float acc[4][4];
#pragma unroll
    for (int i = 0; i < 4; i++)
#pragma unroll
        for (int j = 0; j < 4; j++) acc[i][j] = 0.0f;

    for (int k0 = 0; k0 < 512; k0 += 64) {
#pragma unroll
        for (int l = 0; l < 16; l++) {
            int idx = tid + l * 256;
            int rr = idx >> 6, c = idx & 63;
            xs[rr][c] = x[(size_t)(rowBase + rr) * 512 + k0 + c];
        }
#pragma unroll
        for (int l = 0; l < 16; l++) {
            int idx = tid + l * 256;
            int j = idx >> 6, kk = idx & 63;
            ws[kk][j] = W1[j * 512 + k0 + kk];   // transposed store
        }
        __syncthreads();
#pragma unroll 16
        for (int kk = 0; kk < 64; kk++) {
            float4 wv = *(const float4*)&ws[kk][4 * tx];
            float xv[4];
#pragma unroll
            for (int i = 0; i < 4; i++) xv[i] = xs[4 * ty + i][kk];
#pragma unroll
            for (int i = 0; i < 4; i++) {
                acc[i][0] += xv[i] * wv.x;
                acc[i][1] += xv[i] * wv.y;
                acc[i][2] += xv[i] * wv.z;
                acc[i][3] += xv[i] * wv.w;
            }
        }
        __syncthreads();
    }

    float bb[4];
#pragma unroll
    for (int j = 0; j < 4; j++) bb[j] = b1[4 * tx + j];
#pragma unroll
    for (int i = 0; i < 4; i++) {
        int row = rowBase + 4 * ty + i;
        float4 o;
        o.x = acc[i][0] + bb[0];
        o.y = acc[i][1] + bb[1];
        o.z = acc[i][2] + bb[2];
        o.w = acc[i][3] + bb[3];
        *(float4*)&g_hin[(size_t)row * 64 + 4 * tx] = o;
    }
}

// ---------------------------------------------------------------------------
// Kernel 2: LIF recurrence (layers 1..3), warp per row.
// Spikes carried as ballot masks; emits packed s3 masks per (row, t).
// ---------------------------------------------------------------------------
__global__ void __launch_bounds__(256) k2_recur(const float* __restrict__ W2,
                                                const float* __restrict__ b2,
                                                const float* __restrict__ W3,
                                                const float* __restrict__ b3) {
    __shared__ float W2t[64][16];   // W2t[k][i] = W2[i][k]
    __shared__ float W3t[16][64];   // W3t[i][j] = W3[j][i]
    __shared__ float b2s[16];
    __shared__ float b3s[64];

    const int tid = threadIdx.x;
    for (int i = tid; i < 1024; i += 256) {  // W2 is [16][64]
        int ii = i >> 6, k = i & 63;
        W2t[k][ii] = W2[i];
    }
    for (int i = tid; i < 1024; i += 256) {  // W3 is [64][16]
        int j = i >> 4, ii = i & 15;
        W3t[ii][j] = W3[i];
    }
    if (tid < 16) b2s[tid] = b2[tid];
    if (tid < 64) b3s[tid] = b3[tid];
    __syncthreads();

    const int warp = tid >> 5, lane = tid & 31;
    const int row = blockIdx.x * 8 + warp;

    const float h0 = g_hin[(size_t)row * 64 + lane];
    const float h1 = g_hin[(size_t)row * 64 + 32 + lane];

    float v1a = 0.f, v1b = 0.f, v2 = 0.f, v3a = 0.f, v3b = 0.f;
    unsigned long long mout[8];

#pragma unroll
    for (int t = 0; t < 8; t++) {
        // layer 1 (elementwise; input current constant across t)
        v1a += (h0 - v1a) * 0.5f;
        bool s1a = (v1a - 1.0f) >= 0.0f;
        if (s1a) v1a = 0.0f;
        v1b += (h1 - v1b) * 0.5f;
        bool s1b = (v1b - 1.0f) >= 0.0f;
        if (s1b) v1b = 0.0f;
        unsigned mlo = __ballot_sync(0xffffffffu, s1a);
        unsigned mhi = __ballot_sync(0xffffffffu, s1b);

        // layer 2: I2[i] = b2 + sum over set bits of W2t[k][i]  (lanes 0..15)
        bool s2 = false;
        if (lane < 16) {
            float a = b2s[lane];
#pragma unroll
            for (int k = 0; k < 32; k++)
                if (mlo & (1u << k)) a += W2t[k][lane];
#pragma unroll
            for (int k = 0; k < 32; k++)
                if (mhi & (1u << k)) a += W2t[k + 32][lane];
            v2 += (a - v2) * 0.5f;
            s2 = (v2 - 1.0f) >= 0.0f;
            if (s2) v2 = 0.0f;
        }
        unsigned m2 = __ballot_sync(0xffffffffu, s2);   // bits 16..31 are 0

        // layer 3
        float i3a = b3s[lane];
        float i3b = b3s[lane + 32];
#pragma unroll
        for (int i = 0; i < 16; i++) {
            if (m2 & (1u << i)) {
                i3a += W3t[i][lane];
                i3b += W3t[i][lane + 32];
            }
        }
        v3a += (i3a - v3a) * 0.5f;
        bool s3a = (v3a - 1.0f) >= 0.0f;
        if (s3a) v3a = 0.0f;
        v3b += (i3b - v3b) * 0.5f;
        bool s3b = (v3b - 1.0f) >= 0.0f;
        if (s3b) v3b = 0.0f;

        unsigned olo = __ballot_sync(0xffffffffu, s3a);
        unsigned ohi = __ballot_sync(0xffffffffu, s3b);
        mout[t] = ((unsigned long long)ohi << 32) | (unsigned long long)olo;
    }

    if (lane == 0) {
#pragma unroll
        for (int t = 0; t < 8; t++) g_masks[(size_t)row * 8 + t] = mout[t];
    }
}

// ---------------------------------------------------------------------------
// Kernel 3: out[b][c] = (1/8) * sum_t sigmoid( s3[t,b] . W4[c,:] + b4[c] )
// Block tile: 16 rows x 8 timesteps x 128 cols. Thread: 1 row, 8 t, 8 cols.
// Spikes come from bitmasks; inner product via packed fma.rn.f32x2.
// ---------------------------------------------------------------------------
__global__ void __launch_bounds__(256, 2) k3_out(const float* __restrict__ W4,
                                                 const float* __restrict__ b4,
                                                 float* __restrict__ out) {
    __shared__ float w4s[64][132];   // w4s[k][cc] = W4[c0+cc][k]; 132: pad, 16B-aligned rows
    __shared__ float b4s[128];

    const int tid = threadIdx.x;
    const int c0 = blockIdx.y * 128;
    const int rowBase = blockIdx.x * 16;

    for (int i = tid; i < 64 * 128; i += 256) {
        int cc = i >> 6, k = i & 63;
        w4s[k][cc] = W4[(c0 + cc) * 64 + k];
    }
    if (tid < 128) b4s[tid] = b4[c0 + tid];
    __syncthreads();

    const int r = rowBase + (tid >> 4);
    const int cc = (tid & 15) * 8;

    unsigned mlo[8], mhi[8];
#pragma unroll
    for (int t = 0; t < 8; t++) {
        unsigned long long m = g_masks[(size_t)r * 8 + t];
        mlo[t] = (unsigned)m;
        mhi[t] = (unsigned)(m >> 32);
    }

    unsigned long long bp[4];
#pragma unroll
    for (int p = 0; p < 4; p++) bp[p] = pack2f(b4s[cc + 2 * p], b4s[cc + 2 * p + 1]);

    unsigned long long acc[8][4];
#pragma unroll
    for (int t = 0; t < 8; t++)
#pragma unroll
        for (int p = 0; p < 4; p++) acc[t][p] = bp[p];

#pragma unroll 8
    for (int k = 0; k < 64; k++) {
        ulonglong2 wA = *(const ulonglong2*)&w4s[k][cc];
        ulonglong2 wB = *(const ulonglong2*)&w4s[k][cc + 4];
        const int ks = k & 31;
        const bool hiHalf = (k >= 32);
#pragma unroll
        for (int t = 0; t < 8; t++) {
            unsigned m = hiHalf ? mhi[t] : mlo[t];
            unsigned sb = ((m >> ks) & 1u) * 0x3f800000u;   // 1.0f or 0.0f bits
            unsigned long long sp = pack2u(sb, sb);
            acc[t][0] = fma2(sp, wA.x, acc[t][0]);
            acc[t][1] = fma2(sp, wA.y, acc[t][1]);
            acc[t][2] = fma2(sp, wB.x, acc[t][2]);
            acc[t][3] = fma2(sp, wB.y, acc[t][3]);
        }
    }

    float res[8];
#pragma unroll
    for (int j = 0; j < 8; j++) res[j] = 0.0f;
#pragma unroll
    for (int t = 0; t < 8; t++) {
#pragma unroll
        for (int p = 0; p < 4; p++) {
            float lo, hi;
            unpack2(acc[t][p], lo, hi);
            res[2 * p]     += sigmoidf(lo);
            res[2 * p + 1] += sigmoidf(hi);
        }
    }

    float4 o0, o1;
    o0.x = res[0] * 0.125f; o0.y = res[1] * 0.125f;
    o0.z = res[2] * 0.125f; o0.w = res[3] * 0.125f;
    o1.x = res[4] * 0.125f; o1.y = res[5] * 0.125f;
    o1.z = res[6] * 0.125f; o1.w = res[7] * 0.125f;
    float* dst = &out[(size_t)r * 512 + c0 + cc];
    *(float4*)dst = o0;
    *(float4*)(dst + 4) = o1;
}

// ---------------------------------------------------------------------------
extern "C" void kernel_launch(void* const* d_in, const int* in_sizes, int n_in,
                              void* d_out, int out_size) {
    const float* x  = (const float*)d_in[0];
    const float* W1 = (const float*)d_in[1];
    const float* b1 = (const float*)d_in[2];
    const float* W2 = (const float*)d_in[3];
    const float* b2 = (const float*)d_in[4];
    const float* W3 = (const float*)d_in[5];
    const float* b3 = (const float*)d_in[6];
    const float* W4 = (const float*)d_in[7];
    const float* b4 = (const float*)d_in[8];
    float* out = (float*)d_out;

    k1_hin<<<B_TOTAL / 64, 256>>>(x, W1, b1);
    k2_recur<<<B_TOTAL / 8, 256>>>(W2, b2, W3, b3);
    k3_out<<<dim3(B_TOTAL / 16, 4), 256>>>(W4, b4, out);
}

// round 3
// speedup vs baseline: 1.8238x; 1.8238x over previous
#include <cuda_runtime.h>
#include <cuda_bf16.h>
#include <cstdint>

// SNNAutoencoder: B=65536, D=512, H=64, L=16, T=8
// Inputs: x[65536,512], W1[64,512], b1[64], W2[16,64], b2[16],
//         W3[64,16], b3[64], W4[512,64], b4[512]    Output: float32 [65536,512]

#define B_TOTAL 65536

// Scratch (static device arrays)
__device__ float              g_hin[(size_t)B_TOTAL * 64];      // 16 MB
__device__ unsigned long long g_masks[(size_t)B_TOTAL * 8];     //  4 MB packed s3
__device__ unsigned           g_w4hi[512 * 32];                 // bf16x2 [c][kpair]
__device__ unsigned           g_w4lo[512 * 32];

// ---------------------------------------------------------------------------
// helpers
// ---------------------------------------------------------------------------
__device__ __forceinline__ unsigned long long fma2(unsigned long long a,
                                                   unsigned long long b,
                                                   unsigned long long c) {
    unsigned long long d;
    asm("fma.rn.f32x2 %0, %1, %2, %3;" : "=l"(d) : "l"(a), "l"(b), "l"(c));
    return d;
}
__device__ __forceinline__ unsigned long long pack2f(float a, float b) {
    unsigned long long r;
    asm("mov.b64 %0, {%1, %2};" : "=l"(r) : "f"(a), "f"(b));
    return r;
}
__device__ __forceinline__ void unpack2(unsigned long long v, float& a, float& b) {
    asm("mov.b64 {%0, %1}, %2;" : "=f"(a), "=f"(b) : "l"(v));
}
__device__ __forceinline__ float ex2f(float x) {
    float r;
    asm("ex2.approx.f32 %0, %1;" : "=f"(r) : "f"(x));
    return r;
}
__device__ __forceinline__ float rcpf(float x) {
    float r;
    asm("rcp.approx.f32 %0, %1;" : "=f"(r) : "f"(x));
    return r;
}
// bf16 mma: D(16x8,f32) += A(16x16,bf16,row) * B(16x8,bf16,col)
__device__ __forceinline__ void mma16816(float* d, const unsigned* a,
                                         unsigned b0, unsigned b1) {
    asm volatile(
        "mma.sync.aligned.m16n8k16.row.col.f32.bf16.bf16.f32 "
        "{%0,%1,%2,%3}, {%4,%5,%6,%7}, {%8,%9}, {%0,%1,%2,%3};"
        : "+f"(d[0]), "+f"(d[1]), "+f"(d[2]), "+f"(d[3])
        : "r"(a[0]), "r"(a[1]), "r"(a[2]), "r"(a[3]), "r"(b0), "r"(b1));
}

// ---------------------------------------------------------------------------
// Kernel 0: split W4 into bf16 hi/lo (packed bf16x2 per k-pair)
// ---------------------------------------------------------------------------
__global__ void k0_prep(const float* __restrict__ W4) {
    int idx = blockIdx.x * 256 + threadIdx.x;   // over 512*32 pairs
    if (idx >= 512 * 32) return;
    float w0 = W4[2 * idx], w1 = W4[2 * idx + 1];
    __nv_bfloat16 h0 = __float2bfloat16(w0);
    __nv_bfloat16 h1 = __float2bfloat16(w1);
    __nv_bfloat16 l0 = __float2bfloat16(w0 - __bfloat162float(h0));
    __nv_bfloat16 l1 = __float2bfloat16(w1 - __bfloat162float(h1));
    g_w4hi[idx] = (unsigned)__bfloat16_as_ushort(h0) | ((unsigned)__bfloat16_as_ushort(h1) << 16);
    g_w4lo[idx] = (unsigned)__bfloat16_as_ushort(l0) | ((unsigned)__bfloat16_as_ushort(l1) << 16);
}

// ---------------------------------------------------------------------------
// Kernel 1: h_in[B,64] = x @ W1^T + b1  (FP32 tiled GEMM, packed f32x2 math)
// ---------------------------------------------------------------------------
__global__ void __launch_bounds__(256) k1_hin(const float* __restrict__ x,
                                              const float* __restrict__ W1,
                                              const float* __restrict__ b1) {
    __shared__ float xs[64][68];
    __shared__ float ws[64][68];
    const int tid = threadIdx.x;
    const int tx = tid & 15;
    const int ty = tid >> 4;
    const int rowBase = blockIdx.x * 64;

    unsigned long long acc01[4], acc23[4];
#pragma unroll
    for (int i = 0; i < 4; i++) { acc01[i] = 0ull; acc23[i] = 0ull; }

    for (int k0 = 0; k0 < 512; k0 += 64) {
#pragma unroll
        for (int l = 0; l < 16; l++) {
            int idx = tid + l * 256;
            int rr = idx >> 6, c = idx & 63;
            xs[rr][c] = x[(size_t)(rowBase + rr) * 512 + k0 + c];
        }
#pragma unroll
        for (int l = 0; l < 16; l++) {
            int idx = tid + l * 256;
            int j = idx >> 6, kk = idx & 63;
            ws[kk][j] = W1[j * 512 + k0 + kk];
        }
        __syncthreads();
#pragma unroll 8
        for (int kk = 0; kk < 64; kk++) {
            const ulonglong2* wp = (const ulonglong2*)&ws[kk][4 * tx];
            unsigned long long w01 = wp->x, w23 = wp->y;
#pragma unroll
            for (int i = 0; i < 4; i++) {
                float xv = xs[4 * ty + i][kk];
                unsigned long long xp = pack2f(xv, xv);
                acc01[i] = fma2(xp, w01, acc01[i]);
                acc23[i] = fma2(xp, w23, acc23[i]);
            }
        }
        __syncthreads();
    }

    float bb[4];
#pragma unroll
    for (int j = 0; j < 4; j++) bb[j] = b1[4 * tx + j];
#pragma unroll
    for (int i = 0; i < 4; i++) {
        int row = rowBase + 4 * ty + i;
        float a0, a1, a2, a3;
        unpack2(acc01[i], a0, a1);
        unpack2(acc23[i], a2, a3);
        float4 o;
        o.x = a0 + bb[0]; o.y = a1 + bb[1];
        o.z = a2 + bb[2]; o.w = a3 + bb[3];
        *(float4*)&g_hin[(size_t)row * 64 + 4 * tx] = o;
    }
}

// ---------------------------------------------------------------------------
// Kernel 2: LIF recurrence, warp per row; emits packed s3 masks (unchanged)
// ---------------------------------------------------------------------------
__global__ void __launch_bounds__(256) k2_recur(const float* __restrict__ W2,
                                                const float* __restrict__ b2,
                                                const float* __restrict__ W3,
                                                const float* __restrict__ b3) {
    __shared__ float W2t[64][16];
    __shared__ float W3t[16][64];
    __shared__ float b2s[16];
    __shared__ float b3s[64];

    const int tid = threadIdx.x;
    for (int i = tid; i < 1024; i += 256) {
        int ii = i >> 6, k = i & 63;
        W2t[k][ii] = W2[i];
    }
    for (int i = tid; i < 1024; i += 256) {
        int j = i >> 4, ii = i & 15;
        W3t[ii][j] = W3[i];
    }
    if (tid < 16) b2s[tid] = b2[tid];
    if (tid < 64) b3s[tid] = b3[tid];
    __syncthreads();

    const int warp = tid >> 5, lane = tid & 31;
    const int row = blockIdx.x * 8 + warp;

    const float h0 = g_hin[(size_t)row * 64 + lane];
    const float h1 = g_hin[(size_t)row * 64 + 32 + lane];

    float v1a = 0.f, v1b = 0.f, v2 = 0.f, v3a = 0.f, v3b = 0.f;
    unsigned long long mout[8];

#pragma unroll
    for (int t = 0; t < 8; t++) {
        v1a += (h0 - v1a) * 0.5f;
        bool s1a = (v1a - 1.0f) >= 0.0f;
        if (s1a) v1a = 0.0f;
        v1b += (h1 - v1b) * 0.5f;
        bool s1b = (v1b - 1.0f) >= 0.0f;
        if (s1b) v1b = 0.0f;
        unsigned mlo = __ballot_sync(0xffffffffu, s1a);
        unsigned mhi = __ballot_sync(0xffffffffu, s1b);

        bool s2 = false;
        if (lane < 16) {
            float a = b2s[lane];
#pragma unroll
            for (int k = 0; k < 32; k++)
                if (mlo & (1u << k)) a += W2t[k][lane];
#pragma unroll
            for (int k = 0; k < 32; k++)
                if (mhi & (1u << k)) a += W2t[k + 32][lane];
            v2 += (a - v2) * 0.5f;
            s2 = (v2 - 1.0f) >= 0.0f;
            if (s2) v2 = 0.0f;
        }
        unsigned m2 = __ballot_sync(0xffffffffu, s2);

        float i3a = b3s[lane];
        float i3b = b3s[lane + 32];
#pragma unroll
        for (int i = 0; i < 16; i++) {
            if (m2 & (1u << i)) {
                i3a += W3t[i][lane];
                i3b += W3t[i][lane + 32];
            }
        }
        v3a += (i3a - v3a) * 0.5f;
        bool s3a = (v3a - 1.0f) >= 0.0f;
        if (s3a) v3a = 0.0f;
        v3b += (i3b - v3b) * 0.5f;
        bool s3b = (v3b - 1.0f) >= 0.0f;
        if (s3b) v3b = 0.0f;

        unsigned olo = __ballot_sync(0xffffffffu, s3a);
        unsigned ohi = __ballot_sync(0xffffffffu, s3b);
        mout[t] = ((unsigned long long)ohi << 32) | (unsigned long long)olo;
    }

    if (lane == 0) {
#pragma unroll
        for (int t = 0; t < 8; t++) g_masks[(size_t)row * 8 + t] = mout[t];
    }
}

// ---------------------------------------------------------------------------
// Kernel 3: HMMA (mma.sync m16n8k16 bf16) with W4 hi/lo split.
// GEMM view: M = cols (warp owns 16), N = 8 timesteps of one b, K = 64.
// A = W4 fragments, register-resident for the whole kernel.
// B = spikes, synthesized per-b from the 64-bit mask with shifts/LOP3.
// Epilogue: sigmoid via ex2.approx + rcp.approx, t-mean via shfl.bfly.
// ---------------------------------------------------------------------------
#define K3_BPC 128   // b's per CTA

__global__ void __launch_bounds__(256) k3_mma(const float* __restrict__ b4,
                                              float* __restrict__ out) {
    const int tid = threadIdx.x;
    const int warp = tid >> 5, lane = tid & 31;
    const int g = lane >> 2;        // 0..7 : D row (col offset), B col (t index)
    const int q = lane & 3;         // 0..3 : k sub-index / t-pair in D
    const int colbase = blockIdx.y * 128 + warp * 16;
    const int c0 = colbase + g;
    const int c1 = colbase + g + 8;

    // A fragments (W4 hi/lo), 4 k-steps, loaded once
    unsigned ahi[4][4], alo[4][4];
#pragma unroll
    for (int ks = 0; ks < 4; ks++) {
        ahi[ks][0] = g_w4hi[c0 * 32 + ks * 8 + q];
        ahi[ks][1] = g_w4hi[c1 * 32 + ks * 8 + q];
        ahi[ks][2] = g_w4hi[c0 * 32 + ks * 8 + 4 + q];
        ahi[ks][3] = g_w4hi[c1 * 32 + ks * 8 + 4 + q];
        alo[ks][0] = g_w4lo[c0 * 32 + ks * 8 + q];
        alo[ks][1] = g_w4lo[c1 * 32 + ks * 8 + q];
        alo[ks][2] = g_w4lo[c0 * 32 + ks * 8 + 4 + q];
        alo[ks][3] = g_w4lo[c1 * 32 + ks * 8 + 4 + q];
    }

    const float L2E = 1.4426950408889634f;
    const float e0 = -b4[c0] * L2E;          // folded bias for ex2 arg
    const float e1 = -b4[c1] * L2E;

    const int bbase = blockIdx.x * K3_BPC;

    for (int i = 0; i < K3_BPC; i++) {
        const int b = bbase + i;
        const unsigned long long m = g_masks[(size_t)b * 8 + g];

        // B fragments: bits of mask at k = ks*16 + q*2 + {0,1,8,9}
        unsigned bf[4][2];
#pragma unroll
        for (int ks = 0; ks < 4; ks++) {
            unsigned x = (unsigned)(m >> (ks * 16 + q * 2));
            unsigned s0 = (unsigned)((int)(x << 31) >> 31) & 0x00003F80u;
            unsigned s1 = (unsigned)((int)(x << 30) >> 31) & 0x3F800000u;
            bf[ks][0] = s0 | s1;
            unsigned s2 = (unsigned)((int)(x << 23) >> 31) & 0x00003F80u;
            unsigned s3 = (unsigned)((int)(x << 22) >> 31) & 0x3F800000u;
            bf[ks][1] = s2 | s3;
        }

        float d[4] = {0.f, 0.f, 0.f, 0.f};
#pragma unroll
        for (int ks = 0; ks < 4; ks++) mma16816(d, ahi[ks], bf[ks][0], bf[ks][1]);
#pragma unroll
        for (int ks = 0; ks < 4; ks++) mma16816(d, alo[ks], bf[ks][0], bf[ks][1]);

        // sigmoid(z) = rcp(1 + ex2(-z*log2e)); d0,d1: col c0 (t=2q,2q+1); d2,d3: col c1
        float sA = rcpf(1.0f + ex2f(fmaf(d[0], -L2E, e0)))
                 + rcpf(1.0f + ex2f(fmaf(d[1], -L2E, e0)));
        float sB = rcpf(1.0f + ex2f(fmaf(d[2], -L2E, e1)))
                 + rcpf(1.0f + ex2f(fmaf(d[3], -L2E, e1)));

        // reduce over t across the 4-lane group (q)
        sA += __shfl_xor_sync(0xffffffffu, sA, 1);
        sA += __shfl_xor_sync(0xffffffffu, sA, 2);
        sB += __shfl_xor_sync(0xffffffffu, sB, 1);
        sB += __shfl_xor_sync(0xffffffffu, sB, 2);

        if (q == 0) {
            out[(size_t)b * 512 + c0] = sA * 0.125f;
            out[(size_t)b * 512 + c1] = sB * 0.125f;
        }
    }
}

// ---------------------------------------------------------------------------
extern "C" void kernel_launch(void* const* d_in, const int* in_sizes, int n_in,
                              void* d_out, int out_size) {
    const float* x  = (const float*)d_in[0];
    const float* W1 = (const float*)d_in[1];
    const float* b1 = (const float*)d_in[2];
    const float* W2 = (const float*)d_in[3];
    const float* b2 = (const float*)d_in[4];
    const float* W3 = (const float*)d_in[5];
    const float* b3 = (const float*)d_in[6];
    const float* W4 = (const float*)d_in[7];
    const float* b4 = (const float*)d_in[8];
    float* out = (float*)d_out;

    k0_prep<<<64, 256>>>(W4);
    k1_hin<<<B_TOTAL / 64, 256>>>(x, W1, b1);
    k2_recur<<<B_TOTAL / 8, 256>>>(W2, b2, W3, b3);
    k3_mma<<<dim3(B_TOTAL / K3_BPC, 4), 256>>>(b4, out);
}

// round 4
// speedup vs baseline: 2.8905x; 1.5848x over previous
#include <cuda_runtime.h>
#include <cuda_bf16.h>
#include <cstdint>

// SNNAutoencoder: B=65536, D=512, H=64, L=16, T=8
// Inputs: x[65536,512], W1[64,512], b1[64], W2[16,64], b2[16],
//         W3[64,16], b3[64], W4[512,64], b4[512]    Output: float32 [65536,512]

#define B_TOTAL 65536

// Scratch (static device arrays)
__device__ float              g_hin[(size_t)B_TOTAL * 64];      // 16 MB
__device__ unsigned long long g_masks[(size_t)B_TOTAL * 8];     //  4 MB packed s3
__device__ unsigned           g_w4hi[512 * 32];                 // bf16x2 [c][kpair]
__device__ unsigned           g_w4lo[512 * 32];

// ---------------------------------------------------------------------------
// helpers
// ---------------------------------------------------------------------------
__device__ __forceinline__ unsigned long long fma2(unsigned long long a,
                                                   unsigned long long b,
                                                   unsigned long long c) {
    unsigned long long d;
    asm("fma.rn.f32x2 %0, %1, %2, %3;" : "=l"(d) : "l"(a), "l"(b), "l"(c));
    return d;
}
__device__ __forceinline__ unsigned long long pack2f(float a, float b) {
    unsigned long long r;
    asm("mov.b64 %0, {%1, %2};" : "=l"(r) : "f"(a), "f"(b));
    return r;
}
__device__ __forceinline__ void unpack2(unsigned long long v, float& a, float& b) {
    asm("mov.b64 {%0, %1}, %2;" : "=f"(a), "=f"(b) : "l"(v));
}
__device__ __forceinline__ float ex2f(float x) {
    float r;
    asm("ex2.approx.f32 %0, %1;" : "=f"(r) : "f"(x));
    return r;
}
__device__ __forceinline__ float rcpf(float x) {
    float r;
    asm("rcp.approx.f32 %0, %1;" : "=f"(r) : "f"(x));
    return r;
}
// bf16 mma: D(16x8,f32) += A(16x16,bf16,row) * B(16x8,bf16,col)
__device__ __forceinline__ void mma16816(float* d, const unsigned* a,
                                         unsigned b0, unsigned b1) {
    asm volatile(
        "mma.sync.aligned.m16n8k16.row.col.f32.bf16.bf16.f32 "
        "{%0,%1,%2,%3}, {%4,%5,%6,%7}, {%8,%9}, {%0,%1,%2,%3};"
        : "+f"(d[0]), "+f"(d[1]), "+f"(d[2]), "+f"(d[3])
        : "r"(a[0]), "r"(a[1]), "r"(a[2]), "r"(a[3]), "r"(b0), "r"(b1));
}

// ---------------------------------------------------------------------------
// Kernel 0: split W4 into bf16 hi/lo (packed bf16x2 per k-pair)
// ---------------------------------------------------------------------------
__global__ void k0_prep(const float* __restrict__ W4) {
    int idx = blockIdx.x * 256 + threadIdx.x;   // over 512*32 pairs
    if (idx >= 512 * 32) return;
    float w0 = W4[2 * idx], w1 = W4[2 * idx + 1];
    __nv_bfloat16 h0 = __float2bfloat16(w0);
    __nv_bfloat16 h1 = __float2bfloat16(w1);
    __nv_bfloat16 l0 = __float2bfloat16(w0 - __bfloat162float(h0));
    __nv_bfloat16 l1 = __float2bfloat16(w1 - __bfloat162float(h1));
    g_w4hi[idx] = (unsigned)__bfloat16_as_ushort(h0) | ((unsigned)__bfloat16_as_ushort(h1) << 16);
    g_w4lo[idx] = (unsigned)__bfloat16_as_ushort(l0) | ((unsigned)__bfloat16_as_ushort(l1) << 16);
}

// ---------------------------------------------------------------------------
// Kernel 1: h_in[B,64] = x @ W1^T + b1  (FP32 tiled GEMM, packed f32x2 math)
// ---------------------------------------------------------------------------
__global__ void __launch_bounds__(256) k1_hin(const float* __restrict__ x,
                                              const float* __restrict__ W1,
                                              const float* __restrict__ b1) {
    __shared__ float xs[64][68];
    __shared__ float ws[64][68];
    const int tid = threadIdx.x;
    const int tx = tid & 15;
    const int ty = tid >> 4;
    const int rowBase = blockIdx.x * 64;

    unsigned long long acc01[4], acc23[4];
#pragma unroll
    for (int i = 0; i < 4; i++) { acc01[i] = 0ull; acc23[i] = 0ull; }

    for (int k0 = 0; k0 < 512; k0 += 64) {
#pragma unroll
        for (int l = 0; l < 16; l++) {
            int idx = tid + l * 256;
            int rr = idx >> 6, c = idx & 63;
            xs[rr][c] = x[(size_t)(rowBase + rr) * 512 + k0 + c];
        }
#pragma unroll
        for (int l = 0; l < 16; l++) {
            int idx = tid + l * 256;
            int j = idx >> 6, kk = idx & 63;
            ws[kk][j] = W1[j * 512 + k0 + kk];
        }
        __syncthreads();
#pragma unroll 8
        for (int kk = 0; kk < 64; kk++) {
            const ulonglong2* wp = (const ulonglong2*)&ws[kk][4 * tx];
            unsigned long long w01 = wp->x, w23 = wp->y;
#pragma unroll
            for (int i = 0; i < 4; i++) {
                float xv = xs[4 * ty + i][kk];
                unsigned long long xp = pack2f(xv, xv);
                acc01[i] = fma2(xp, w01, acc01[i]);
                acc23[i] = fma2(xp, w23, acc23[i]);
            }
        }
        __syncthreads();
    }

    float bb[4];
#pragma unroll
    for (int j = 0; j < 4; j++) bb[j] = b1[4 * tx + j];
#pragma unroll
    for (int i = 0; i < 4; i++) {
        int row = rowBase + 4 * ty + i;
        float a0, a1, a2, a3;
        unpack2(acc01[i], a0, a1);
        unpack2(acc23[i], a2, a3);
        float4 o;
        o.x = a0 + bb[0]; o.y = a1 + bb[1];
        o.z = a2 + bb[2]; o.w = a3 + bb[3];
        *(float4*)&g_hin[(size_t)row * 64 + 4 * tx] = o;
    }
}

// ---------------------------------------------------------------------------
// Kernel 2: LIF recurrence with nibble LUTs (masks are warp-uniform ->
// broadcast LDS). Warp handles 4 rows for ILP. 2048 CTAs x 256 thr.
// ---------------------------------------------------------------------------
__global__ void __launch_bounds__(256) k2_recur(const float* __restrict__ W2,
                                                const float* __restrict__ b2,
                                                const float* __restrict__ W3,
                                                const float* __restrict__ b3) {
    __shared__ float LUT2[16 * 16 * 16];   // [np][nv][i]   16KB
    __shared__ float LUT3[4 * 16 * 64];    // [np][nv][j]   16KB
    __shared__ float W2t[64][17];
    __shared__ float W3t[16][65];
    __shared__ float b2s[16];
    __shared__ float b3s[64];

    const int tid = threadIdx.x;
    for (int i = tid; i < 1024; i += 256) {        // W2 [16][64]
        int ii = i >> 6, k = i & 63;
        W2t[k][ii] = W2[i];
    }
    for (int i = tid; i < 1024; i += 256) {        // W3 [64][16]
        int j = i >> 4, ii = i & 15;
        W3t[ii][j] = W3[i];
    }
    if (tid < 16) b2s[tid] = b2[tid];
    if (tid < 64) b3s[tid] = b3[tid];
    __syncthreads();

    for (int e = tid; e < 4096; e += 256) {
        int np = e >> 8, nv = (e >> 4) & 15, i = e & 15;
        float s = 0.0f;
#pragma unroll
        for (int j = 0; j < 4; j++)
            if (nv & (1 << j)) s += W2t[np * 4 + j][i];
        LUT2[e] = s;
    }
    for (int e = tid; e < 4096; e += 256) {
        int np = e >> 10, nv = (e >> 6) & 15, j = e & 63;
        float s = 0.0f;
#pragma unroll
        for (int jj = 0; jj < 4; jj++)
            if (nv & (1 << jj)) s += W3t[np * 4 + jj][j];
        LUT3[e] = s;
    }
    __syncthreads();

    const int warp = tid >> 5, lane = tid & 31;
    const int row0 = blockIdx.x * 32 + warp * 4;
    const int iL = lane & 15;
    const int half = lane >> 4;
    const float b2v = b2s[iL];
    const float b3a = b3s[lane];
    const float b3b = b3s[lane + 32];

    float h0[4], h1[4];
    float v1a[4], v1b[4], v2[4], v3a[4], v3b[4];
#pragma unroll
    for (int r = 0; r < 4; r++) {
        h0[r] = g_hin[(size_t)(row0 + r) * 64 + lane];
        h1[r] = g_hin[(size_t)(row0 + r) * 64 + 32 + lane];
        v1a[r] = v1b[r] = v2[r] = v3a[r] = v3b[r] = 0.0f;
    }

    for (int t = 0; t < 8; t++) {
        unsigned mlo[4], mhi[4];
#pragma unroll
        for (int r = 0; r < 4; r++) {
            v1a[r] += (h0[r] - v1a[r]) * 0.5f;
            bool s1a = v1a[r] >= 1.0f;
            if (s1a) v1a[r] = 0.0f;
            v1b[r] += (h1[r] - v1b[r]) * 0.5f;
            bool s1b = v1b[r] >= 1.0f;
            if (s1b) v1b[r] = 0.0f;
            mlo[r] = __ballot_sync(0xffffffffu, s1a);
            mhi[r] = __ballot_sync(0xffffffffu, s1b);
        }

        unsigned long long mo[4];
#pragma unroll
        for (int r = 0; r < 4; r++) {
            // layer 2 via LUT2 (mask warp-uniform -> broadcast LDS)
            unsigned w = half ? mhi[r] : mlo[r];
            float p2 = 0.0f;
#pragma unroll
            for (int p = 0; p < 8; p++) {
                unsigned nv = (w >> (4 * p)) & 15u;
                p2 += LUT2[(half * 8 + p) * 256 + nv * 16 + iL];
            }
            p2 += __shfl_xor_sync(0xffffffffu, p2, 16);
            float a2 = b2v + p2;
            v2[r] += (a2 - v2[r]) * 0.5f;
            bool s2 = v2[r] >= 1.0f;
            if (s2) v2[r] = 0.0f;
            unsigned m2 = __ballot_sync(0xffffffffu, s2) & 0xFFFFu;

            // layer 3 via LUT3
            float i3a = b3a, i3b = b3b;
#pragma unroll
            for (int p = 0; p < 4; p++) {
                unsigned nv = (m2 >> (4 * p)) & 15u;
                const float* L = &LUT3[p * 1024 + nv * 64];
                i3a += L[lane];
                i3b += L[lane + 32];
            }
            v3a[r] += (i3a - v3a[r]) * 0.5f;
            bool s3a = v3a[r] >= 1.0f;
            if (s3a) v3a[r] = 0.0f;
            v3b[r] += (i3b - v3b[r]) * 0.5f;
            bool s3b = v3b[r] >= 1.0f;
            if (s3b) v3b[r] = 0.0f;

            unsigned olo = __ballot_sync(0xffffffffu, s3a);
            unsigned ohi = __ballot_sync(0xffffffffu, s3b);
            mo[r] = ((unsigned long long)ohi << 32) | (unsigned long long)olo;
        }

        unsigned long long mm = (lane == 0) ? mo[0] :
                                (lane == 1) ? mo[1] :
                                (lane == 2) ? mo[2] : mo[3];
        if (lane < 4) g_masks[(size_t)(row0 + lane) * 8 + t] = mm;
    }
}

// ---------------------------------------------------------------------------
// Kernel 3: HMMA with smem-staged B-fragments.
// Chunks of 16 b's: each warp synthesizes frags for 2 b's -> smem; all warps
// consume all 16 (2 LDS.128 + 8 MMA + sigmoid/mean epilogue per b).
// ---------------------------------------------------------------------------
#define K3_BPC 128

__global__ void __launch_bounds__(256) k3_mma(const float* __restrict__ b4,
                                              float* __restrict__ out) {
    __shared__ uint4 sfA[16][32];   // [b][lane] : ks0/ks1 frag words, 8KB
    __shared__ uint4 sfB[16][32];   // ks2/ks3, 8KB

    const int tid = threadIdx.x;
    const int warp = tid >> 5, lane = tid & 31;
    const int g = lane >> 2;        // t index / D row offset
    const int q = lane & 3;
    const int colbase = blockIdx.y * 128 + warp * 16;
    const int c0 = colbase + g;
    const int c1 = colbase + g + 8;

    // A fragments (W4 hi/lo), register-resident
    unsigned ahi[4][4], alo[4][4];
#pragma unroll
    for (int ks = 0; ks < 4; ks++) {
        ahi[ks][0] = g_w4hi[c0 * 32 + ks * 8 + q];
        ahi[ks][1] = g_w4hi[c1 * 32 + ks * 8 + q];
        ahi[ks][2] = g_w4hi[c0 * 32 + ks * 8 + 4 + q];
        ahi[ks][3] = g_w4hi[c1 * 32 + ks * 8 + 4 + q];
        alo[ks][0] = g_w4lo[c0 * 32 + ks * 8 + q];
        alo[ks][1] = g_w4lo[c1 * 32 + ks * 8 + q];
        alo[ks][2] = g_w4lo[c0 * 32 + ks * 8 + 4 + q];
        alo[ks][3] = g_w4lo[c1 * 32 + ks * 8 + 4 + q];
    }

    const float L2E = 1.4426950408889634f;
    const float e0 = -b4[c0] * L2E;
    const float e1 = -b4[c1] * L2E;

    const int bbase = blockIdx.x * K3_BPC;

    for (int cb = 0; cb < K3_BPC; cb += 16) {
        // produce: this warp synthesizes B-frags for b = bbase+cb+warp, +8
#pragma unroll
        for (int s = 0; s < 2; s++) {
            const int bi = warp + s * 8;
            const unsigned long long m = g_masks[(size_t)(bbase + cb + bi) * 8 + g];
            unsigned bf[4][2];
#pragma unroll
            for (int ks = 0; ks < 4; ks++) {
                unsigned x = (unsigned)(m >> (ks * 16 + q * 2));
                unsigned s0 = (unsigned)((int)(x << 31) >> 31) & 0x00003F80u;
                unsigned s1 = (unsigned)((int)(x << 30) >> 31) & 0x3F800000u;
                bf[ks][0] = s0 | s1;
                unsigned s2 = (unsigned)((int)(x << 23) >> 31) & 0x00003F80u;
                unsigned s3 = (unsigned)((int)(x << 22) >> 31) & 0x3F800000u;
                bf[ks][1] = s2 | s3;
            }
            sfA[bi][lane] = make_uint4(bf[0][0], bf[0][1], bf[1][0], bf[1][1]);
            sfB[bi][lane] = make_uint4(bf[2][0], bf[2][1], bf[3][0], bf[3][1]);
        }
        __syncthreads();

        // consume all 16 b's
#pragma unroll 4
        for (int i = 0; i < 16; i++) {
            uint4 fa = sfA[i][lane];
            uint4 fb = sfB[i][lane];

            float dh[4] = {0.f, 0.f, 0.f, 0.f};
            float dl[4] = {0.f, 0.f, 0.f, 0.f};
            mma16816(dh, ahi[0], fa.x, fa.y);
            mma16816(dl, alo[0], fa.x, fa.y);
            mma16816(dh, ahi[1], fa.z, fa.w);
            mma16816(dl, alo[1], fa.z, fa.w);
            mma16816(dh, ahi[2], fb.x, fb.y);
            mma16816(dl, alo[2], fb.x, fb.y);
            mma16816(dh, ahi[3], fb.z, fb.w);
            mma16816(dl, alo[3], fb.z, fb.w);

            float sA = rcpf(1.0f + ex2f(fmaf(dh[0] + dl[0], -L2E, e0)))
                     + rcpf(1.0f + ex2f(fmaf(dh[1] + dl[1], -L2E, e0)));
            float sB = rcpf(1.0f + ex2f(fmaf(dh[2] + dl[2], -L2E, e1)))
                     + rcpf(1.0f + ex2f(fmaf(dh[3] + dl[3], -L2E, e1)));

            sA += __shfl_xor_sync(0xffffffffu, sA, 1);
            sA += __shfl_xor_sync(0xffffffffu, sA, 2);
            sB += __shfl_xor_sync(0xffffffffu, sB, 1);
            sB += __shfl_xor_sync(0xffffffffu, sB, 2);

            if (q == 0) {
                const int b = bbase + cb + i;
                out[(size_t)b * 512 + c0] = sA * 0.125f;
                out[(size_t)b * 512 + c1] = sB * 0.125f;
            }
        }
        __syncthreads();
    }
}

// ---------------------------------------------------------------------------
extern "C" void kernel_launch(void* const* d_in, const int* in_sizes, int n_in,
                              void* d_out, int out_size) {
    const float* x  = (const float*)d_in[0];
    const float* W1 = (const float*)d_in[1];
    const float* b1 = (const float*)d_in[2];
    const float* W2 = (const float*)d_in[3];
    const float* b2 = (const float*)d_in[4];
    const float* W3 = (const float*)d_in[5];
    const float* b3 = (const float*)d_in[6];
    const float* W4 = (const float*)d_in[7];
    const float* b4 = (const float*)d_in[8];
    float* out = (float*)d_out;

    k0_prep<<<64, 256>>>(W4);
    k1_hin<<<B_TOTAL / 64, 256>>>(x, W1, b1);
    k2_recur<<<B_TOTAL / 32, 256>>>(W2, b2, W3, b3);
    k3_mma<<<dim3(B_TOTAL / K3_BPC, 4), 256>>>(b4, out);
}

// round 5
// speedup vs baseline: 3.4314x; 1.1871x over previous
#include <cuda_runtime.h>
#include <cuda_bf16.h>
#include <cstdint>

// SNNAutoencoder: B=65536, D=512, H=64, L=16, T=8
// Inputs: x[65536,512], W1[64,512], b1[64], W2[16,64], b2[16],
//         W3[64,16], b3[64], W4[512,64], b4[512]    Output: float32 [65536,512]

#define B_TOTAL 65536

// Scratch (static device arrays)
__device__ float              g_hin[(size_t)B_TOTAL * 64];      // 16 MB
__device__ unsigned long long g_masks[(size_t)B_TOTAL * 8];     //  4 MB packed s3
__device__ unsigned           g_w4hi[512 * 32];                 // bf16x2 [c][kpair]
__device__ unsigned           g_w4lo[512 * 32];
__device__ float2             g_w1hi[64 * 64 * 4];              // tf32 pairs [ks][n][q]
__device__ float2             g_w1lo[64 * 64 * 4];

// ---------------------------------------------------------------------------
// helpers
// ---------------------------------------------------------------------------
__device__ __forceinline__ float tanhf_approx(float x) {
    float r;
    asm("tanh.approx.f32 %0, %1;" : "=f"(r) : "f"(x));
    return r;
}
__device__ __forceinline__ unsigned cvt_tf32(float f) {
    unsigned u;
    asm("cvt.rna.tf32.f32 %0, %1;" : "=r"(u) : "f"(f));
    return u;
}
// bf16 mma: D(16x8,f32) += A(16x16,bf16,row) * B(16x8,bf16,col)
__device__ __forceinline__ void mma16816(float* d, const unsigned* a,
                                         unsigned b0, unsigned b1) {
    asm volatile(
        "mma.sync.aligned.m16n8k16.row.col.f32.bf16.bf16.f32 "
        "{%0,%1,%2,%3}, {%4,%5,%6,%7}, {%8,%9}, {%0,%1,%2,%3};"
        : "+f"(d[0]), "+f"(d[1]), "+f"(d[2]), "+f"(d[3])
        : "r"(a[0]), "r"(a[1]), "r"(a[2]), "r"(a[3]), "r"(b0), "r"(b1));
}
// tf32 mma: D(16x8,f32) += A(16x8,tf32,row) * B(8x8,tf32,col)
__device__ __forceinline__ void mma1688t(float* d, const unsigned* a,
                                         unsigned b0, unsigned b1) {
    asm volatile(
        "mma.sync.aligned.m16n8k8.row.col.f32.tf32.tf32.f32 "
        "{%0,%1,%2,%3}, {%4,%5,%6,%7}, {%8,%9}, {%0,%1,%2,%3};"
        : "+f"(d[0]), "+f"(d[1]), "+f"(d[2]), "+f"(d[3])
        : "r"(a[0]), "r"(a[1]), "r"(a[2]), "r"(a[3]), "r"(b0), "r"(b1));
}

// ---------------------------------------------------------------------------
// Kernel 0a: split W4 into bf16 hi/lo (packed bf16x2 per k-pair)
// ---------------------------------------------------------------------------
__global__ void k0_prep(const float* __restrict__ W4) {
    int idx = blockIdx.x * 256 + threadIdx.x;   // over 512*32 pairs
    if (idx >= 512 * 32) return;
    float w0 = W4[2 * idx], w1 = W4[2 * idx + 1];
    __nv_bfloat16 h0 = __float2bfloat16(w0);
    __nv_bfloat16 h1 = __float2bfloat16(w1);
    __nv_bfloat16 l0 = __float2bfloat16(w0 - __bfloat162float(h0));
    __nv_bfloat16 l1 = __float2bfloat16(w1 - __bfloat162float(h1));
    g_w4hi[idx] = (unsigned)__bfloat16_as_ushort(h0) | ((unsigned)__bfloat16_as_ushort(h1) << 16);
    g_w4lo[idx] = (unsigned)__bfloat16_as_ushort(l0) | ((unsigned)__bfloat16_as_ushort(l1) << 16);
}

// ---------------------------------------------------------------------------
// Kernel 0b: pack W1 as tf32 hi/lo B-fragment pairs.
// Entry (ks, n, q): {W1[n][8ks+q], W1[n][8ks+q+4]} -> (b0, b1) of m16n8k8.
// ---------------------------------------------------------------------------
__global__ void k0_w1(const float* __restrict__ W1) {
    int idx = blockIdx.x * 256 + threadIdx.x;   // over 64*64*4
    if (idx >= 64 * 64 * 4) return;
    int ks = idx >> 8, n = (idx >> 2) & 63, q = idx & 3;
    float w0 = W1[n * 512 + ks * 8 + q];
    float w4 = W1[n * 512 + ks * 8 + q + 4];
    unsigned h0 = cvt_tf32(w0), h4 = cvt_tf32(w4);
    unsigned l0 = cvt_tf32(w0 - __uint_as_float(h0));
    unsigned l4 = cvt_tf32(w4 - __uint_as_float(h4));
    g_w1hi[idx] = make_float2(__uint_as_float(h0), __uint_as_float(h4));
    g_w1lo[idx] = make_float2(__uint_as_float(l0), __uint_as_float(l4));
}

// ---------------------------------------------------------------------------
// Kernel 1: h_in = x @ W1^T + b1 via 3xTF32 mma.sync (fp32-equivalent).
// CTA = 128 rows (8 warps x 16). W1 frags staged in 64KB smem, 16-kstep chunks.
// ---------------------------------------------------------------------------
__global__ void __launch_bounds__(256) k1_hin(const float* __restrict__ x,
                                              const float* __restrict__ b1) {
    extern __shared__ float2 sw[];          // [16][64][4] hi, then lo (4096 each)
    float2* whi = sw;
    float2* wlo = sw + 4096;

    const int tid = threadIdx.x;
    const int warp = tid >> 5, lane = tid & 31;
    const int g = lane >> 2, q = lane & 3;
    const int row0 = blockIdx.x * 128 + warp * 16;

    float d[8][4];
#pragma unroll
    for (int j = 0; j < 8; j++)
#pragma unroll
        for (int i = 0; i < 4; i++) d[j][i] = 0.0f;

    const float* xr0 = x + (size_t)(row0 + g) * 512;
    const float* xr1 = x + (size_t)(row0 + g + 8) * 512;

    for (int ch = 0; ch < 4; ch++) {
        __syncthreads();
        const float2* sh = g_w1hi + ch * 4096;
        const float2* sl = g_w1lo + ch * 4096;
        for (int i = tid; i < 4096; i += 256) {
            whi[i] = sh[i];
            wlo[i] = sl[i];
        }
        __syncthreads();

#pragma unroll 4
        for (int ks = 0; ks < 16; ks++) {
            const int kg = ch * 128 + ks * 8;
            float a0f = xr0[kg + q];
            float a1f = xr1[kg + q];
            float a2f = xr0[kg + q + 4];
            float a3f = xr1[kg + q + 4];
            unsigned ahi[4], alo[4];
            ahi[0] = cvt_tf32(a0f); alo[0] = cvt_tf32(a0f - __uint_as_float(ahi[0]));
            ahi[1] = cvt_tf32(a1f); alo[1] = cvt_tf32(a1f - __uint_as_float(ahi[1]));
            ahi[2] = cvt_tf32(a2f); alo[2] = cvt_tf32(a2f - __uint_as_float(ahi[2]));
            ahi[3] = cvt_tf32(a3f); alo[3] = cvt_tf32(a3f - __uint_as_float(ahi[3]));

            const int base = ks * 256 + g * 4 + q;
#pragma unroll
            for (int j = 0; j < 8; j++) {
                float2 h = whi[base + j * 32];
                float2 l = wlo[base + j * 32];
                unsigned hb0 = __float_as_uint(h.x), hb1 = __float_as_uint(h.y);
                unsigned lb0 = __float_as_uint(l.x), lb1 = __float_as_uint(l.y);
                mma1688t(d[j], ahi, hb0, hb1);
                mma1688t(d[j], ahi, lb0, lb1);
                mma1688t(d[j], alo, hb0, hb1);
            }
        }
    }

    // epilogue: rows row0+g, row0+g+8; cols 8j+2q, 8j+2q+1
    float* o0 = &g_hin[(size_t)(row0 + g) * 64];
    float* o1 = &g_hin[(size_t)(row0 + g + 8) * 64];
#pragma unroll
    for (int j = 0; j < 8; j++) {
        const float2 bb = *(const float2*)&b1[8 * j + 2 * q];
        float2 v0 = make_float2(d[j][0] + bb.x, d[j][1] + bb.y);
        float2 v1 = make_float2(d[j][2] + bb.x, d[j][3] + bb.y);
        *(float2*)&o0[8 * j + 2 * q] = v0;
        *(float2*)&o1[8 * j + 2 * q] = v1;
    }
}

// ---------------------------------------------------------------------------
// Kernel 2: LIF recurrence with nibble LUTs; warp handles 8 rows.
// LUT2 [16np][16nv][16i] 16KB; LUT3p [4np][16nv][32j] float2 32KB (= 48KB).
// ---------------------------------------------------------------------------
__global__ void __launch_bounds__(256) k2_recur(const float* __restrict__ W2,
                                                const float* __restrict__ b2,
                                                const float* __restrict__ W3,
                                                const float* __restrict__ b3) {
    __shared__ float  LUT2[16 * 16 * 16];
    __shared__ float2 LUT3p[4 * 16 * 32];

    const int tid = threadIdx.x;
    for (int e = tid; e < 4096; e += 256) {
        int np = e >> 8, nv = (e >> 4) & 15, i = e & 15;
        float s = 0.0f;
#pragma unroll
        for (int j = 0; j < 4; j++)
            if (nv & (1 << j)) s += W2[i * 64 + np * 4 + j];
        LUT2[e] = s;
    }
    for (int e = tid; e < 2048; e += 256) {
        int np = e >> 9, nv = (e >> 5) & 15, j = e & 31;
        float sx = 0.0f, sy = 0.0f;
#pragma unroll
        for (int jj = 0; jj < 4; jj++)
            if (nv & (1 << jj)) {
                sx += W3[j * 16 + np * 4 + jj];
                sy += W3[(j + 32) * 16 + np * 4 + jj];
            }
        LUT3p[e] = make_float2(sx, sy);
    }
    __syncthreads();

    const int warp = tid >> 5, lane = tid & 31;
    const int row0 = blockIdx.x * 64 + warp * 8;
    const int iL = lane & 15;
    const int half = lane >> 4;
    const float b2v = b2[iL];
    const float b3a = b3[lane];
    const float b3b = b3[lane + 32];

    float h0[8], h1[8], v1a[8], v1b[8], v2[8], v3a[8], v3b[8];
#pragma unroll
    for (int r = 0; r < 8; r++) {
        h0[r] = g_hin[(size_t)(row0 + r) * 64 + lane];
        h1[r] = g_hin[(size_t)(row0 + r) * 64 + 32 + lane];
        v1a[r] = v1b[r] = v2[r] = v3a[r] = v3b[r] = 0.0f;
    }

    for (int t = 0; t < 8; t++) {
        unsigned mlo[8], mhi[8];
#pragma unroll
        for (int r = 0; r < 8; r++) {
            v1a[r] += (h0[r] - v1a[r]) * 0.5f;
            bool s1a = v1a[r] >= 1.0f;
            if (s1a) v1a[r] = 0.0f;
            v1b[r] += (h1[r] - v1b[r]) * 0.5f;
            bool s1b = v1b[r] >= 1.0f;
            if (s1b) v1b[r] = 0.0f;
            mlo[r] = __ballot_sync(0xffffffffu, s1a);
            mhi[r] = __ballot_sync(0xffffffffu, s1b);
        }

#pragma unroll
        for (int r = 0; r < 8; r++) {
            unsigned w = half ? mhi[r] : mlo[r];
            float p2 = 0.0f;
#pragma unroll
            for (int p = 0; p < 8; p++) {
                unsigned nv = (w >> (4 * p)) & 15u;
                p2 += LUT2[(half * 8 + p) * 256 + nv * 16 + iL];
            }
            p2 += __shfl_xor_sync(0xffffffffu, p2, 16);
            float a2 = b2v + p2;
            v2[r] += (a2 - v2[r]) * 0.5f;
            bool s2 = v2[r] >= 1.0f;
            if (s2) v2[r] = 0.0f;
            unsigned m2 = __ballot_sync(0xffffffffu, s2) & 0xFFFFu;

            float i3a = b3a, i3b = b3b;
#pragma unroll
            for (int p = 0; p < 4; p++) {
                unsigned nv = (m2 >> (4 * p)) & 15u;
                float2 L = LUT3p[(p * 16 + nv) * 32 + lane];
                i3a += L.x;
                i3b += L.y;
            }
            v3a[r] += (i3a - v3a[r]) * 0.5f;
            bool s3a = v3a[r] >= 1.0f;
            if (s3a) v3a[r] = 0.0f;
            v3b[r] += (i3b - v3b[r]) * 0.5f;
            bool s3b = v3b[r] >= 1.0f;
            if (s3b) v3b[r] = 0.0f;

            unsigned olo = __ballot_sync(0xffffffffu, s3a);
            unsigned ohi = __ballot_sync(0xffffffffu, s3b);
            unsigned long long mo = ((unsigned long long)ohi << 32) | (unsigned long long)olo;
            if (lane == r) g_masks[(size_t)(row0 + r) * 8 + t] = mo;
        }
    }
}

// ---------------------------------------------------------------------------
// Kernel 3: HMMA with smem-staged B-fragments; sigmoid via tanh.approx.
// ---------------------------------------------------------------------------
#define K3_BPC 128

__global__ void __launch_bounds__(256) k3_mma(const float* __restrict__ b4,
                                              float* __restrict__ out) {
    __shared__ uint4 sfA[16][32];
    __shared__ uint4 sfB[16][32];

    const int tid = threadIdx.x;
    const int warp = tid >> 5, lane = tid & 31;
    const int g = lane >> 2;
    const int q = lane & 3;
    const int colbase = blockIdx.y * 128 + warp * 16;
    const int c0 = colbase + g;
    const int c1 = colbase + g + 8;

    unsigned ahi[4][4], alo[4][4];
#pragma unroll
    for (int ks = 0; ks < 4; ks++) {
        ahi[ks][0] = g_w4hi[c0 * 32 + ks * 8 + q];
        ahi[ks][1] = g_w4hi[c1 * 32 + ks * 8 + q];
        ahi[ks][2] = g_w4hi[c0 * 32 + ks * 8 + 4 + q];
        ahi[ks][3] = g_w4hi[c1 * 32 + ks * 8 + 4 + q];
        alo[ks][0] = g_w4lo[c0 * 32 + ks * 8 + q];
        alo[ks][1] = g_w4lo[c1 * 32 + ks * 8 + q];
        alo[ks][2] = g_w4lo[c0 * 32 + ks * 8 + 4 + q];
        alo[ks][3] = g_w4lo[c1 * 32 + ks * 8 + 4 + q];
    }

    // sigmoid(z) = 0.5 + 0.5*tanh(z/2); fold bias: arg = 0.5*d + 0.5*b4[c]
    const float e0 = 0.5f * b4[c0];
    const float e1 = 0.5f * b4[c1];

    const int bbase = blockIdx.x * K3_BPC;

    for (int cb = 0; cb < K3_BPC; cb += 16) {
#pragma unroll
        for (int s = 0; s < 2; s++) {
            const int bi = warp + s * 8;
            const unsigned long long m = g_masks[(size_t)(bbase + cb + bi) * 8 + g];
            unsigned bf[4][2];
#pragma unroll
            for (int ks = 0; ks < 4; ks++) {
                unsigned x = (unsigned)(m >> (ks * 16 + q * 2));
                unsigned s0 = (unsigned)((int)(x << 31) >> 31) & 0x00003F80u;
                unsigned s1 = (unsigned)((int)(x << 30) >> 31) & 0x3F800000u;
                bf[ks][0] = s0 | s1;
                unsigned s2 = (unsigned)((int)(x << 23) >> 31) & 0x00003F80u;
                unsigned s3 = (unsigned)((int)(x << 22) >> 31) & 0x3F800000u;
                bf[ks][1] = s2 | s3;
            }
            sfA[bi][lane] = make_uint4(bf[0][0], bf[0][1], bf[1][0], bf[1][1]);
            sfB[bi][lane] = make_uint4(bf[2][0], bf[2][1], bf[3][0], bf[3][1]);
        }
        __syncthreads();

#pragma unroll 4
        for (int i = 0; i < 16; i++) {
            uint4 fa = sfA[i][lane];
            uint4 fb = sfB[i][lane];

            float dh[4] = {0.f, 0.f, 0.f, 0.f};
            float dl[4] = {0.f, 0.f, 0.f, 0.f};
            mma16816(dh, ahi[0], fa.x, fa.y);
            mma16816(dl, alo[0], fa.x, fa.y);
            mma16816(dh, ahi[1], fa.z, fa.w);
            mma16816(dl, alo[1], fa.z, fa.w);
            mma16816(dh, ahi[2], fb.x, fb.y);
            mma16816(dl, alo[2], fb.x, fb.y);
            mma16816(dh, ahi[3], fb.z, fb.w);
            mma16816(dl, alo[3], fb.z, fb.w);

            float tA0 = tanhf_approx(fmaf(dh[0] + dl[0], 0.5f, e0));
            float tA1 = tanhf_approx(fmaf(dh[1] + dl[1], 0.5f, e0));
            float tB0 = tanhf_approx(fmaf(dh[2] + dl[2], 0.5f, e1));
            float tB1 = tanhf_approx(fmaf(dh[3] + dl[3], 0.5f, e1));
            float pA = tA0 + tA1;
            float pB = tB0 + tB1;

            pA += __shfl_xor_sync(0xffffffffu, pA, 1);
            pA += __shfl_xor_sync(0xffffffffu, pA, 2);
            pB += __shfl_xor_sync(0xffffffffu, pB, 1);
            pB += __shfl_xor_sync(0xffffffffu, pB, 2);

            if (q == 0) {
                const int b = bbase + cb + i;
                // mean of 8 sigmoids = 0.5 + (sum tanh)/16
                out[(size_t)b * 512 + c0] = fmaf(pA, 0.0625f, 0.5f);
                out[(size_t)b * 512 + c1] = fmaf(pB, 0.0625f, 0.5f);
            }
        }
        __syncthreads();
    }
}

// ---------------------------------------------------------------------------
extern "C" void kernel_launch(void* const* d_in, const int* in_sizes, int n_in,
                              void* d_out, int out_size) {
    const float* x  = (const float*)d_in[0];
    const float* W1 = (const float*)d_in[1];
    const float* b1 = (const float*)d_in[2];
    const float* W2 = (const float*)d_in[3];
    const float* b2 = (const float*)d_in[4];
    const float* W3 = (const float*)d_in[5];
    const float* b3 = (const float*)d_in[6];
    const float* W4 = (const float*)d_in[7];
    const float* b4 = (const float*)d_in[8];
    float* out = (float*)d_out;

    static bool attr_set = false;
    if (!attr_set) {
        cudaFuncSetAttribute(k1_hin, cudaFuncAttributeMaxDynamicSharedMemorySize, 65536);
        attr_set = true;
    }

    k0_prep<<<64, 256>>>(W4);
    k0_w1<<<64, 256>>>(W1);
    k1_hin<<<B_TOTAL / 128, 256, 65536>>>(x, b1);
    k2_recur<<<B_TOTAL / 64, 256>>>(W2, b2, W3, b3);
    k3_mma<<<dim3(B_TOTAL / K3_BPC, 4), 256>>>(b4, out);
}

// round 6
// speedup vs baseline: 4.1079x; 1.1971x over previous
#include <cuda_runtime.h>
#include <cuda_fp16.h>
#include <cstdint>

// SNNAutoencoder: B=65536, D=512, H=64, L=16, T=8
// Inputs: x[65536,512], W1[64,512], b1[64], W2[16,64], b2[16],
//         W3[64,16], b3[64], W4[512,64], b4[512]    Output: float32 [65536,512]

#define B_TOTAL 65536

// Scratch (static device arrays)
__device__ float              g_hin[(size_t)B_TOTAL * 64];      // 16 MB
__device__ unsigned long long g_masks[(size_t)B_TOTAL * 8];     //  4 MB packed s3
__device__ unsigned           g_w4f[512 * 32];                  // fp16x2 [c][kpair]
__device__ float2             g_w1hi[64 * 64 * 4];              // tf32 pairs [ks][n][q]
__device__ float2             g_w1lo[64 * 64 * 4];

// ---------------------------------------------------------------------------
// helpers
// ---------------------------------------------------------------------------
__device__ __forceinline__ unsigned tanh2(unsigned h) {
    unsigned r;
    asm("tanh.approx.f16x2 %0, %1;" : "=r"(r) : "r"(h));
    return r;
}
__device__ __forceinline__ unsigned cvt_tf32(float f) {
    unsigned u;
    asm("cvt.rna.tf32.f32 %0, %1;" : "=r"(u) : "f"(f));
    return u;
}
// fp16 mma: D(16x8,f32) += A(16x16,f16,row) * B(16x8,f16,col)
__device__ __forceinline__ void mma16816h(float* d, const unsigned* a,
                                          unsigned b0, unsigned b1) {
    asm volatile(
        "mma.sync.aligned.m16n8k16.row.col.f32.f16.f16.f32 "
        "{%0,%1,%2,%3}, {%4,%5,%6,%7}, {%8,%9}, {%0,%1,%2,%3};"
        : "+f"(d[0]), "+f"(d[1]), "+f"(d[2]), "+f"(d[3])
        : "r"(a[0]), "r"(a[1]), "r"(a[2]), "r"(a[3]), "r"(b0), "r"(b1));
}
// tf32 mma: D(16x8,f32) += A(16x8,tf32,row) * B(8x8,tf32,col)
__device__ __forceinline__ void mma1688t(float* d, const unsigned* a,
                                         unsigned b0, unsigned b1) {
    asm volatile(
        "mma.sync.aligned.m16n8k8.row.col.f32.tf32.tf32.f32 "
        "{%0,%1,%2,%3}, {%4,%5,%6,%7}, {%8,%9}, {%0,%1,%2,%3};"
        : "+f"(d[0]), "+f"(d[1]), "+f"(d[2]), "+f"(d[3])
        : "r"(a[0]), "r"(a[1]), "r"(a[2]), "r"(a[3]), "r"(b0), "r"(b1));
}

// ---------------------------------------------------------------------------
// Kernel 0: pack W4 (fp16x2) and W1 (tf32 hi/lo fragment pairs)
// ---------------------------------------------------------------------------
__global__ void k0_pack(const float* __restrict__ W4,
                        const float* __restrict__ W1) {
    const int bid = blockIdx.x;
    const int idx = (bid & 63) * 256 + threadIdx.x;   // 0..16383
    if (bid < 64) {
        // W4 fp16 pack: entry = (c, kpair)
        float w0 = W4[2 * idx], w1 = W4[2 * idx + 1];
        __half h0 = __float2half_rn(w0);
        __half h1 = __float2half_rn(w1);
        g_w4f[idx] = (unsigned)__half_as_ushort(h0) |
                     ((unsigned)__half_as_ushort(h1) << 16);
    } else {
        // W1 tf32 hi/lo: entry (ks, n, q) -> {W1[n][8ks+q], W1[n][8ks+q+4]}
        int ks = idx >> 8, n = (idx >> 2) & 63, q = idx & 3;
        float w0 = W1[n * 512 + ks * 8 + q];
        float w4 = W1[n * 512 + ks * 8 + q + 4];
        unsigned h0 = cvt_tf32(w0), h4 = cvt_tf32(w4);
        unsigned l0 = cvt_tf32(w0 - __uint_as_float(h0));
        unsigned l4 = cvt_tf32(w4 - __uint_as_float(h4));
        g_w1hi[idx] = make_float2(__uint_as_float(h0), __uint_as_float(h4));
        g_w1lo[idx] = make_float2(__uint_as_float(l0), __uint_as_float(l4));
    }
}

// ---------------------------------------------------------------------------
// Kernel 1: h_in = x @ W1^T + b1 via 3xTF32 mma.sync (fp32-equivalent).
// x staged through smem (coalesced float4 LDG, conflict-free padded LDS).
// CTA = 128 rows; 8 chunks of K=64. Dyn smem = 67584 B -> 3 CTAs/SM.
// ---------------------------------------------------------------------------
__global__ void __launch_bounds__(256) k1_hin(const float* __restrict__ x,
                                              const float* __restrict__ b1) {
    extern __shared__ float smemf[];
    float*  xs = smemf;                       // [128][68]  34816 B
    float2* wh = (float2*)(smemf + 8704);     // [2048]     16384 B
    float2* wl = wh + 2048;                   // [2048]     16384 B

    const int tid = threadIdx.x;
    const int warp = tid >> 5, lane = tid & 31;
    const int g = lane >> 2, q = lane & 3;
    const int blockRow = blockIdx.x * 128;

    float d[8][4];
#pragma unroll
    for (int j = 0; j < 8; j++)
#pragma unroll
        for (int i = 0; i < 4; i++) d[j][i] = 0.0f;

    const int r0 = warp * 16 + g;      // CTA-local rows
    const int r1 = r0 + 8;

    for (int ch = 0; ch < 8; ch++) {
        __syncthreads();
        // stage x tile [128][64]
        const float* xsrc = x + (size_t)blockRow * 512 + ch * 64;
#pragma unroll
        for (int it = 0; it < 8; it++) {
            int fidx = it * 256 + tid;
            int rr = fidx >> 4, c4 = (fidx & 15) * 4;
            float4 v = *(const float4*)(xsrc + (size_t)rr * 512 + c4);
            *(float4*)&xs[rr * 68 + c4] = v;
        }
        // stage W1 fragment chunk
        const float2* sh = g_w1hi + ch * 2048;
        const float2* sl = g_w1lo + ch * 2048;
        for (int i = tid; i < 2048; i += 256) {
            wh[i] = sh[i];
            wl[i] = sl[i];
        }
        __syncthreads();

#pragma unroll
        for (int ks = 0; ks < 8; ks++) {
            const int lc = ks * 8 + q;
            float a0f = xs[r0 * 68 + lc];
            float a1f = xs[r1 * 68 + lc];
            float a2f = xs[r0 * 68 + lc + 4];
            float a3f = xs[r1 * 68 + lc + 4];
            unsigned ahi[4], alo[4];
            ahi[0] = cvt_tf32(a0f); alo[0] = cvt_tf32(a0f - __uint_as_float(ahi[0]));
            ahi[1] = cvt_tf32(a1f); alo[1] = cvt_tf32(a1f - __uint_as_float(ahi[1]));
            ahi[2] = cvt_tf32(a2f); alo[2] = cvt_tf32(a2f - __uint_as_float(ahi[2]));
            ahi[3] = cvt_tf32(a3f); alo[3] = cvt_tf32(a3f - __uint_as_float(ahi[3]));

            const int base = ks * 256 + g * 4 + q;
#pragma unroll
            for (int j = 0; j < 8; j++) {
                float2 h = wh[base + j * 32];
                float2 l = wl[base + j * 32];
                unsigned hb0 = __float_as_uint(h.x), hb1 = __float_as_uint(h.y);
                unsigned lb0 = __float_as_uint(l.x), lb1 = __float_as_uint(l.y);
                mma1688t(d[j], ahi, hb0, hb1);
                mma1688t(d[j], ahi, lb0, lb1);
                mma1688t(d[j], alo, hb0, hb1);
            }
        }
    }

    float* o0 = &g_hin[(size_t)(blockRow + r0) * 64];
    float* o1 = &g_hin[(size_t)(blockRow + r1) * 64];
#pragma unroll
    for (int j = 0; j < 8; j++) {
        const float2 bb = *(const float2*)&b1[8 * j + 2 * q];
        float2 v0 = make_float2(d[j][0] + bb.x, d[j][1] + bb.y);
        float2 v1 = make_float2(d[j][2] + bb.x, d[j][3] + bb.y);
        *(float2*)&o0[8 * j + 2 * q] = v0;
        *(float2*)&o1[8 * j + 2 * q] = v1;
    }
}

// ---------------------------------------------------------------------------
// Kernel 2: LIF recurrence with nibble LUTs; warp handles 8 rows.
// ---------------------------------------------------------------------------
__global__ void __launch_bounds__(256) k2_recur(const float* __restrict__ W2,
                                                const float* __restrict__ b2,
                                                const float* __restrict__ W3,
                                                const float* __restrict__ b3) {
    __shared__ float  LUT2[16 * 16 * 16];
    __shared__ float2 LUT3p[4 * 16 * 32];

    const int tid = threadIdx.x;
    for (int e = tid; e < 4096; e += 256) {
        int np = e >> 8, nv = (e >> 4) & 15, i = e & 15;
        float s = 0.0f;
#pragma unroll
        for (int j = 0; j < 4; j++)
            if (nv & (1 << j)) s += W2[i * 64 + np * 4 + j];
        LUT2[e] = s;
    }
    for (int e = tid; e < 2048; e += 256) {
        int np = e >> 9, nv = (e >> 5) & 15, j = e & 31;
        float sx = 0.0f, sy = 0.0f;
#pragma unroll
        for (int jj = 0; jj < 4; jj++)
            if (nv & (1 << jj)) {
                sx += W3[j * 16 + np * 4 + jj];
                sy += W3[(j + 32) * 16 + np * 4 + jj];
            }
        LUT3p[e] = make_float2(sx, sy);
    }
    __syncthreads();

    const int warp = tid >> 5, lane = tid & 31;
    const int row0 = blockIdx.x * 64 + warp * 8;
    const int iL = lane & 15;
    const int half = lane >> 4;
    const float b2v = b2[iL];
    const float b3a = b3[lane];
    const float b3b = b3[lane + 32];

    float h0[8], h1[8], v1a[8], v1b[8], v2[8], v3a[8], v3b[8];
#pragma unroll
    for (int r = 0; r < 8; r++) {
        h0[r] = g_hin[(size_t)(row0 + r) * 64 + lane];
        h1[r] = g_hin[(size_t)(row0 + r) * 64 + 32 + lane];
        v1a[r] = v1b[r] = v2[r] = v3a[r] = v3b[r] = 0.0f;
    }

    for (int t = 0; t < 8; t++) {
        unsigned mlo[8], mhi[8];
#pragma unroll
        for (int r = 0; r < 8; r++) {
            v1a[r] += (h0[r] - v1a[r]) * 0.5f;
            bool s1a = v1a[r] >= 1.0f;
            if (s1a) v1a[r] = 0.0f;
            v1b[r] += (h1[r] - v1b[r]) * 0.5f;
            bool s1b = v1b[r] >= 1.0f;
            if (s1b) v1b[r] = 0.0f;
            mlo[r] = __ballot_sync(0xffffffffu, s1a);
            mhi[r] = __ballot_sync(0xffffffffu, s1b);
        }

#pragma unroll
        for (int r = 0; r < 8; r++) {
            unsigned w = half ? mhi[r] : mlo[r];
            float p2 = 0.0f;
#pragma unroll
            for (int p = 0; p < 8; p++) {
                unsigned nv = (w >> (4 * p)) & 15u;
                p2 += LUT2[(half * 8 + p) * 256 + nv * 16 + iL];
            }
            p2 += __shfl_xor_sync(0xffffffffu, p2, 16);
            float a2 = b2v + p2;
            v2[r] += (a2 - v2[r]) * 0.5f;
            bool s2 = v2[r] >= 1.0f;
            if (s2) v2[r] = 0.0f;
            unsigned m2 = __ballot_sync(0xffffffffu, s2) & 0xFFFFu;

            float i3a = b3a, i3b = b3b;
#pragma unroll
            for (int p = 0; p < 4; p++) {
                unsigned nv = (m2 >> (4 * p)) & 15u;
                float2 L = LUT3p[(p * 16 + nv) * 32 + lane];
                i3a += L.x;
                i3b += L.y;
            }
            v3a[r] += (i3a - v3a[r]) * 0.5f;
            bool s3a = v3a[r] >= 1.0f;
            if (s3a) v3a[r] = 0.0f;
            v3b[r] += (i3b - v3b[r]) * 0.5f;
            bool s3b = v3b[r] >= 1.0f;
            if (s3b) v3b[r] = 0.0f;

            unsigned olo = __ballot_sync(0xffffffffu, s3a);
            unsigned ohi = __ballot_sync(0xffffffffu, s3b);
            unsigned long long mo = ((unsigned long long)ohi << 32) | (unsigned long long)olo;
            if (lane == r) g_masks[(size_t)(row0 + r) * 8 + t] = mo;
        }
    }
}

// ---------------------------------------------------------------------------
// Kernel 3: single fp16 HMMA (4 MMAs/b) + tanh.approx.f16x2 epilogue.
// ---------------------------------------------------------------------------
#define K3_BPC 128

__global__ void __launch_bounds__(256) k3_mma(const float* __restrict__ b4,
                                              float* __restrict__ out) {
    __shared__ uint4 sfA[16][32];   // ks0/ks1 frag words
    __shared__ uint4 sfB[16][32];   // ks2/ks3

    const int tid = threadIdx.x;
    const int warp = tid >> 5, lane = tid & 31;
    const int g = lane >> 2;
    const int q = lane & 3;
    const int colbase = blockIdx.y * 128 + warp * 16;
    const int c0 = colbase + g;
    const int c1 = colbase + g + 8;

    unsigned af[4][4];
#pragma unroll
    for (int ks = 0; ks < 4; ks++) {
        af[ks][0] = g_w4f[c0 * 32 + ks * 8 + q];
        af[ks][1] = g_w4f[c1 * 32 + ks * 8 + q];
        af[ks][2] = g_w4f[c0 * 32 + ks * 8 + 4 + q];
        af[ks][3] = g_w4f[c1 * 32 + ks * 8 + 4 + q];
    }

    // sigmoid(z) = 0.5 + 0.5*tanh(z/2); fold bias
    const float e0 = 0.5f * b4[c0];
    const float e1 = 0.5f * b4[c1];

    const int bbase = blockIdx.x * K3_BPC;

    for (int cb = 0; cb < K3_BPC; cb += 16) {
#pragma unroll
        for (int s = 0; s < 2; s++) {
            const int bi = warp + s * 8;
            const unsigned long long m = g_masks[(size_t)(bbase + cb + bi) * 8 + g];
            unsigned bf[4][2];
#pragma unroll
            for (int ks = 0; ks < 4; ks++) {
                unsigned x = (unsigned)(m >> (ks * 16 + q * 2));
                unsigned s0 = (unsigned)((int)(x << 31) >> 31) & 0x00003C00u;
                unsigned s1 = (unsigned)((int)(x << 30) >> 31) & 0x3C000000u;
                bf[ks][0] = s0 | s1;
                unsigned s2 = (unsigned)((int)(x << 23) >> 31) & 0x00003C00u;
                unsigned s3 = (unsigned)((int)(x << 22) >> 31) & 0x3C000000u;
                bf[ks][1] = s2 | s3;
            }
            sfA[bi][lane] = make_uint4(bf[0][0], bf[0][1], bf[1][0], bf[1][1]);
            sfB[bi][lane] = make_uint4(bf[2][0], bf[2][1], bf[3][0], bf[3][1]);
        }
        __syncthreads();

#pragma unroll 4
        for (int i = 0; i < 16; i++) {
            uint4 fa = sfA[i][lane];
            uint4 fb = sfB[i][lane];

            float d[4] = {0.f, 0.f, 0.f, 0.f};
            mma16816h(d, af[0], fa.x, fa.y);
            mma16816h(d, af[1], fa.z, fa.w);
            mma16816h(d, af[2], fb.x, fb.y);
            mma16816h(d, af[3], fb.z, fb.w);

            // two tanh.f16x2: (t=2q, 2q+1) for col c0 and col c1
            __half2 hA = __floats2half2_rn(fmaf(d[0], 0.5f, e0),
                                           fmaf(d[1], 0.5f, e0));
            __half2 hB = __floats2half2_rn(fmaf(d[2], 0.5f, e1),
                                           fmaf(d[3], 0.5f, e1));
            unsigned tA = tanh2(*(unsigned*)&hA);
            unsigned tB = tanh2(*(unsigned*)&hB);
            float2 fA = __half22float2(*(__half2*)&tA);
            float2 fB = __half22float2(*(__half2*)&tB);
            float pA = fA.x + fA.y;
            float pB = fB.x + fB.y;

            pA += __shfl_xor_sync(0xffffffffu, pA, 1);
            pA += __shfl_xor_sync(0xffffffffu, pA, 2);
            pB += __shfl_xor_sync(0xffffffffu, pB, 1);
            pB += __shfl_xor_sync(0xffffffffu, pB, 2);

            if (q == 0) {
                const int b = bbase + cb + i;
                out[(size_t)b * 512 + c0] = fmaf(pA, 0.0625f, 0.5f);
                out[(size_t)b * 512 + c1] = fmaf(pB, 0.0625f, 0.5f);
            }
        }
        __syncthreads();
    }
}

// ---------------------------------------------------------------------------
extern "C" void kernel_launch(void* const* d_in, const int* in_sizes, int n_in,
                              void* d_out, int out_size) {
    const float* x  = (const float*)d_in[0];
    const float* W1 = (const float*)d_in[1];
    const float* b1 = (const float*)d_in[2];
    const float* W2 = (const float*)d_in[3];
    const float* b2 = (const float*)d_in[4];
    const float* W3 = (const float*)d_in[5];
    const float* b3 = (const float*)d_in[6];
    const float* W4 = (const float*)d_in[7];
    const float* b4 = (const float*)d_in[8];
    float* out = (float*)d_out;

    static bool attr_set = false;
    if (!attr_set) {
        cudaFuncSetAttribute(k1_hin, cudaFuncAttributeMaxDynamicSharedMemorySize, 67584);
        attr_set = true;
    }

    k0_pack<<<128, 256>>>(W4, W1);
    k1_hin<<<B_TOTAL / 128, 256, 67584>>>(x, b1);
    k2_recur<<<B_TOTAL / 64, 256>>>(W2, b2, W3, b3);
    k3_mma<<<dim3(B_TOTAL / K3_BPC, 4), 256>>>(b4, out);
}